// round 2
// baseline (speedup 1.0000x reference)
#include <cuda_runtime.h>
#include <math.h>

#define NTOK 4096
#define NH   16
#define HD   72
#define HID  1152
#define PROJ 1152

// Scratch (allowed: __device__ globals, no runtime allocation)
__device__ float g_q [NTOK * PROJ];
__device__ float g_k [NTOK * PROJ];
__device__ float g_v [NTOK * PROJ];
__device__ float g_ao[NTOK * PROJ];

// ---------------------------------------------------------------------------
// Generic 64x64 tiled fp32 GEMM body: C[M,Nn] = A[M,K] @ B[K,Nn] (row-major)
// 256 threads, 4x4 register microtile, float4 global loads.
// ---------------------------------------------------------------------------
__device__ __forceinline__ void gemm_body(const float* __restrict__ A,
                                          const float* __restrict__ B,
                                          float* __restrict__ C,
                                          int M, int Nn, int K) {
    __shared__ float As[16 * 65];   // [k][m], padded stride 65
    __shared__ float Bs[16 * 64];   // [k][n]

    const int tid = threadIdx.x;
    const int n0 = blockIdx.x * 64;
    const int m0 = blockIdx.y * 64;

    const int ty = tid >> 4;          // 0..15 (row group)
    const int tx = tid & 15;          // 0..15 (col group)

    const int ar = tid >> 2;          // 0..63  A row
    const int ac = (tid & 3) * 4;     // 0,4,8,12  A k-col (float4)
    const int br = tid >> 4;          // 0..15  B k-row
    const int bc = (tid & 15) * 4;    // 0..60  B n-col (float4)

    float acc[4][4];
#pragma unroll
    for (int i = 0; i < 4; ++i)
#pragma unroll
        for (int j = 0; j < 4; ++j) acc[i][j] = 0.0f;

    for (int k0 = 0; k0 < K; k0 += 16) {
        float4 av = *(const float4*)(A + (long)(m0 + ar) * K + k0 + ac);
        float4 bv = *(const float4*)(B + (long)(k0 + br) * Nn + n0 + bc);

        __syncthreads();
        As[(ac + 0) * 65 + ar] = av.x;
        As[(ac + 1) * 65 + ar] = av.y;
        As[(ac + 2) * 65 + ar] = av.z;
        As[(ac + 3) * 65 + ar] = av.w;
        *(float4*)(Bs + br * 64 + bc) = bv;
        __syncthreads();

#pragma unroll
        for (int kk = 0; kk < 16; ++kk) {
            float ra[4];
#pragma unroll
            for (int i = 0; i < 4; ++i) ra[i] = As[kk * 65 + ty * 4 + i];
            float4 rb = *(const float4*)(Bs + kk * 64 + tx * 4);
#pragma unroll
            for (int i = 0; i < 4; ++i) {
                acc[i][0] += ra[i] * rb.x;
                acc[i][1] += ra[i] * rb.y;
                acc[i][2] += ra[i] * rb.z;
                acc[i][3] += ra[i] * rb.w;
            }
        }
    }

#pragma unroll
    for (int i = 0; i < 4; ++i) {
        float4 o = make_float4(acc[i][0], acc[i][1], acc[i][2], acc[i][3]);
        *(float4*)(C + (long)(m0 + ty * 4 + i) * Nn + n0 + tx * 4) = o;
    }
}

__global__ __launch_bounds__(256) void gemm_qkv_kernel(const float* __restrict__ X,
                                                       const float* __restrict__ Wq,
                                                       const float* __restrict__ Wk,
                                                       const float* __restrict__ Wv) {
    const float* B = (blockIdx.z == 0) ? Wq : (blockIdx.z == 1 ? Wk : Wv);
    float* C = (blockIdx.z == 0) ? g_q : (blockIdx.z == 1 ? g_k : g_v);
    gemm_body(X, B, C, NTOK, PROJ, HID);
}

__global__ __launch_bounds__(256) void gemm_out_kernel(const float* __restrict__ Wo,
                                                       float* __restrict__ out) {
    gemm_body(g_ao, Wo, out, NTOK, HID, PROJ);
}

// ---------------------------------------------------------------------------
// Per (token, head): RMSNorm q (w/ q_scale), k (w/ k_scale), v (no weight);
// then 2D RoPE on q and k. One warp per (token, head), in-place.
// ---------------------------------------------------------------------------
__global__ __launch_bounds__(128) void norm_rope_kernel(const float* __restrict__ cosb,
                                                        const float* __restrict__ sinb,
                                                        const float* __restrict__ qsc,
                                                        const float* __restrict__ ksc) {
    __shared__ float bq[4][HD];
    __shared__ float bk[4][HD];

    const int w = threadIdx.x >> 5;
    const int lane = threadIdx.x & 31;
    const int pair = blockIdx.x * 4 + w;           // = n*16 + h
    const int n = pair >> 4;

    float* qp = g_q + (long)pair * HD;
    float* kp = g_k + (long)pair * HD;
    float* vp = g_v + (long)pair * HD;

    float q0 = qp[lane], q1 = qp[lane + 32], q2 = (lane < 8) ? qp[lane + 64] : 0.0f;
    float k0 = kp[lane], k1 = kp[lane + 32], k2 = (lane < 8) ? kp[lane + 64] : 0.0f;
    float v0 = vp[lane], v1 = vp[lane + 32], v2 = (lane < 8) ? vp[lane + 64] : 0.0f;

    float sq = q0 * q0 + q1 * q1 + q2 * q2;
    float sk = k0 * k0 + k1 * k1 + k2 * k2;
    float sv = v0 * v0 + v1 * v1 + v2 * v2;
#pragma unroll
    for (int o = 16; o > 0; o >>= 1) {
        sq += __shfl_xor_sync(0xffffffffu, sq, o);
        sk += __shfl_xor_sync(0xffffffffu, sk, o);
        sv += __shfl_xor_sync(0xffffffffu, sv, o);
    }
    const float iq = rsqrtf(sq * (1.0f / HD) + 1e-6f);
    const float ik = rsqrtf(sk * (1.0f / HD) + 1e-6f);
    const float iv = rsqrtf(sv * (1.0f / HD) + 1e-6f);

    // v: normalized, no weight, no rope
    vp[lane] = v0 * iv;
    vp[lane + 32] = v1 * iv;
    if (lane < 8) vp[lane + 64] = v2 * iv;

    // q,k: normalized*scale into smem, then rope
    bq[w][lane]      = q0 * iq * qsc[lane];
    bq[w][lane + 32] = q1 * iq * qsc[lane + 32];
    bk[w][lane]      = k0 * ik * ksc[lane];
    bk[w][lane + 32] = k1 * ik * ksc[lane + 32];
    if (lane < 8) {
        bq[w][lane + 64] = q2 * iq * qsc[lane + 64];
        bk[w][lane + 64] = k2 * ik * ksc[lane + 64];
    }
    __syncwarp();

    const float* cr = cosb + (long)n * HD;
    const float* sr = sinb + (long)n * HD;
#pragma unroll
    for (int e = 0; e < 3; ++e) {
        int d = lane + 32 * e;
        if (d < HD) {
            float c = cr[d], s = sr[d];
            int loc = d % 36;
            int prt = (loc < 18) ? d + 18 : d - 18;
            float sgn = (loc < 18) ? -1.0f : 1.0f;
            qp[d] = bq[w][d] * c + sgn * bq[w][prt] * s;
            kp[d] = bk[w][d] * c + sgn * bk[w][prt] * s;
        }
    }
}

// ---------------------------------------------------------------------------
// Flash attention, fp32, no scale factor (matches reference einsum+softmax).
// Grid: (NTOK/64 q-tiles, 16 heads). Block: 256 threads.
// BQ=64 q rows, streamed K/V tiles of BK=32 rows.
// Phase A: S = Q @ K^T  (4 rows x 2 cols microtile, 16x16 thread grid)
// Phase B: online softmax + acc += P @ V  (2 rows x 9 dims per thread)
// ---------------------------------------------------------------------------
#define BQ 64
#define BK 32
#define QP 73   // padded head-dim stride (odd -> conflict-free)
#define SP 33   // padded score stride

__global__ __launch_bounds__(256) void attn_kernel() {
    __shared__ float Qs[BQ * QP];
    __shared__ float Ks[BK * QP];
    __shared__ float Vs[BK * QP];
    __shared__ float Ss[BQ * SP];

    const int h = blockIdx.y;
    const int q0 = blockIdx.x * BQ;
    const int tid = threadIdx.x;

    // Phase A mapping
    const int ty = tid >> 4;   // 0..15 -> q rows ty*4..ty*4+3
    const int tx = tid & 15;   // 0..15 -> k cols tx*2, tx*2+1
    // Phase B mapping
    const int rg = tid >> 3;   // 0..31 -> rows rg*2, rg*2+1
    const int dg = tid & 7;    // 0..7  -> dims dg*9..dg*9+8
    const int r0 = rg * 2, r1 = rg * 2 + 1;

    // Load Q tile
    for (int idx = tid; idx < BQ * HD; idx += 256) {
        int r = idx / HD, d = idx - r * HD;
        Qs[r * QP + d] = g_q[(long)(q0 + r) * PROJ + h * HD + d];
    }

    float acc0[9], acc1[9];
#pragma unroll
    for (int i = 0; i < 9; ++i) { acc0[i] = 0.0f; acc1[i] = 0.0f; }
    float m0 = -1e30f, m1 = -1e30f, l0 = 0.0f, l1 = 0.0f;

    for (int j = 0; j < NTOK / BK; ++j) {
        const int kbase = j * BK;
        __syncthreads();   // prior-iter Vs/Ss reads done (also covers Q load, iter 0)
        for (int idx = tid; idx < BK * HD; idx += 256) {
            int r = idx / HD, d = idx - r * HD;
            long g = (long)(kbase + r) * PROJ + h * HD + d;
            Ks[r * QP + d] = g_k[g];
            Vs[r * QP + d] = g_v[g];
        }
        __syncthreads();

        // ---- Phase A: scores ----
        float s[4][2];
#pragma unroll
        for (int i = 0; i < 4; ++i) { s[i][0] = 0.0f; s[i][1] = 0.0f; }
#pragma unroll 8
        for (int d = 0; d < HD; ++d) {
            float qv[4], kv[2];
#pragma unroll
            for (int i = 0; i < 4; ++i) qv[i] = Qs[(ty * 4 + i) * QP + d];
            kv[0] = Ks[(tx * 2 + 0) * QP + d];
            kv[1] = Ks[(tx * 2 + 1) * QP + d];
#pragma unroll
            for (int i = 0; i < 4; ++i) {
                s[i][0] += qv[i] * kv[0];
                s[i][1] += qv[i] * kv[1];
            }
        }
#pragma unroll
        for (int i = 0; i < 4; ++i) {
            Ss[(ty * 4 + i) * SP + tx * 2 + 0] = s[i][0];
            Ss[(ty * 4 + i) * SP + tx * 2 + 1] = s[i][1];
        }
        __syncthreads();

        // ---- Online softmax for rows r0, r1 (8 threads per row) ----
        {
            float tmax0 = -1e30f, tmax1 = -1e30f;
#pragma unroll
            for (int i = 0; i < 4; ++i) {
                tmax0 = fmaxf(tmax0, Ss[r0 * SP + dg * 4 + i]);
                tmax1 = fmaxf(tmax1, Ss[r1 * SP + dg * 4 + i]);
            }
#pragma unroll
            for (int o = 4; o > 0; o >>= 1) {
                tmax0 = fmaxf(tmax0, __shfl_xor_sync(0xffffffffu, tmax0, o));
                tmax1 = fmaxf(tmax1, __shfl_xor_sync(0xffffffffu, tmax1, o));
            }
            float mn0 = fmaxf(m0, tmax0);
            float mn1 = fmaxf(m1, tmax1);
            float sc0 = __expf(m0 - mn0);
            float sc1 = __expf(m1 - mn1);
            float ls0 = 0.0f, ls1 = 0.0f;
#pragma unroll
            for (int i = 0; i < 4; ++i) {
                float p0 = __expf(Ss[r0 * SP + dg * 4 + i] - mn0);
                float p1 = __expf(Ss[r1 * SP + dg * 4 + i] - mn1);
                Ss[r0 * SP + dg * 4 + i] = p0;
                Ss[r1 * SP + dg * 4 + i] = p1;
                ls0 += p0; ls1 += p1;
            }
#pragma unroll
            for (int o = 4; o > 0; o >>= 1) {
                ls0 += __shfl_xor_sync(0xffffffffu, ls0, o);
                ls1 += __shfl_xor_sync(0xffffffffu, ls1, o);
            }
            l0 = l0 * sc0 + ls0;
            l1 = l1 * sc1 + ls1;
            m0 = mn0; m1 = mn1;
#pragma unroll
            for (int i = 0; i < 9; ++i) { acc0[i] *= sc0; acc1[i] *= sc1; }
        }
        __syncwarp();

        // ---- Phase B: acc += P @ V ----
#pragma unroll 4
        for (int kk = 0; kk < BK; ++kk) {
            float p0 = Ss[r0 * SP + kk];
            float p1 = Ss[r1 * SP + kk];
#pragma unroll
            for (int i = 0; i < 9; ++i) {
                float v = Vs[kk * QP + dg * 9 + i];
                acc0[i] += p0 * v;
                acc1[i] += p1 * v;
            }
        }
    }

    // Epilogue
    const float il0 = 1.0f / l0;
    const float il1 = 1.0f / l1;
#pragma unroll
    for (int i = 0; i < 9; ++i) {
        g_ao[(long)(q0 + r0) * PROJ + h * HD + dg * 9 + i] = acc0[i] * il0;
        g_ao[(long)(q0 + r1) * PROJ + h * HD + dg * 9 + i] = acc1[i] * il1;
    }
}

// ---------------------------------------------------------------------------
extern "C" void kernel_launch(void* const* d_in, const int* in_sizes, int n_in,
                              void* d_out, int out_size) {
    const float* X    = (const float*)d_in[0];
    const float* cosb = (const float*)d_in[1];
    const float* sinb = (const float*)d_in[2];
    const float* Wq   = (const float*)d_in[3];
    const float* Wk   = (const float*)d_in[4];
    const float* Wv   = (const float*)d_in[5];
    const float* Wo   = (const float*)d_in[6];
    const float* qsc  = (const float*)d_in[7];
    const float* ksc  = (const float*)d_in[8];
    float* out = (float*)d_out;

    gemm_qkv_kernel<<<dim3(PROJ / 64, NTOK / 64, 3), 256>>>(X, Wq, Wk, Wv);
    norm_rope_kernel<<<(NTOK * NH) / 4, 128>>>(cosb, sinb, qsc, ksc);
    attn_kernel<<<dim3(NTOK / BQ, NH), 256>>>();
    gemm_out_kernel<<<dim3(HID / 64, NTOK / 64), 256>>>(Wo, out);
}

// round 3
// speedup vs baseline: 1.5727x; 1.5727x over previous
#include <cuda_runtime.h>
#include <math.h>

#define NTOK 4096
#define NH   16
#define HD   72
#define HID  1152
#define PROJ 1152

// Scratch (allowed: __device__ globals, no runtime allocation)
__device__ float g_q [NTOK * PROJ];
__device__ float g_k [NTOK * PROJ];
__device__ float g_v [NTOK * PROJ];
__device__ float g_ao[NTOK * PROJ];

// ---------------------------------------------------------------------------
// tf32 helpers: split fp32 into hi (tf32, round-to-nearest) + lo residual.
// 3xTF32: D += Ahi*Bhi + Ahi*Blo + Alo*Bhi  ->  ~fp32 accuracy on tensor pipe
// ---------------------------------------------------------------------------
__device__ __forceinline__ void tf32_split(float x, unsigned& hi, unsigned& lo) {
    unsigned h;
    asm("cvt.rna.tf32.f32 %0, %1;" : "=r"(h) : "f"(x));
    hi = h;
    lo = __float_as_uint(x - __uint_as_float(h));
}

__device__ __forceinline__ void mma_tf32(float d[4], const unsigned a[4],
                                         unsigned b0, unsigned b1) {
    asm volatile(
        "mma.sync.aligned.m16n8k8.row.col.f32.tf32.tf32.f32 "
        "{%0,%1,%2,%3}, {%4,%5,%6,%7}, {%8,%9}, {%0,%1,%2,%3};\n"
        : "+f"(d[0]), "+f"(d[1]), "+f"(d[2]), "+f"(d[3])
        : "r"(a[0]), "r"(a[1]), "r"(a[2]), "r"(a[3]), "r"(b0), "r"(b1));
}

__device__ __forceinline__ void mma3(float d[4],
                                     const unsigned ah[4], const unsigned al[4],
                                     unsigned bh0, unsigned bh1,
                                     unsigned bl0, unsigned bl1) {
    mma_tf32(d, ah, bh0, bh1);
    mma_tf32(d, ah, bl0, bl1);
    mma_tf32(d, al, bh0, bh1);
}

// ---------------------------------------------------------------------------
// 3xTF32 GEMM: C[4096,1152] = A[4096,1152] @ B[1152,1152], row-major.
// Block 256 thr (8 warps, 2x4), tile 64x128, BK=16. Warp tile 32x32.
// Smem strides chosen conflict-free for mma fragment gather patterns.
// ---------------------------------------------------------------------------
#define GAST 20    // A smem stride (16 + 4): 20*qr+qc distinct mod 32
#define GBST 136   // B smem stride (128 + 8): 8*qc+qr distinct mod 32

__device__ __forceinline__ void gemm3_body(const float* __restrict__ A,
                                           const float* __restrict__ Bm,
                                           float* __restrict__ C) {
    __shared__ float As[64 * GAST];
    __shared__ float Bs[16 * GBST];

    const int tid  = threadIdx.x;
    const int lane = tid & 31;
    const int wid  = tid >> 5;
    const int wm = wid >> 2, wn = wid & 3;       // 2 x 4 warp grid
    const int qr = lane >> 2, qc = lane & 3;

    const int m0 = blockIdx.y * 64;
    const int n0 = blockIdx.x * 128;

    const int ar = tid >> 2;          // A row 0..63
    const int ac = (tid & 3) * 4;     // A k-col {0,4,8,12}
    const int br = tid >> 5;          // B k-row 0..7 (and +8)
    const int bc = (tid & 31) * 4;    // B n-col

    float acc[2][4][4] = {};

    for (int k0 = 0; k0 < 1152; k0 += 16) {
        float4 av  = *(const float4*)(A  + (long)(m0 + ar) * 1152 + k0 + ac);
        float4 bv0 = *(const float4*)(Bm + (long)(k0 + br) * 1152 + n0 + bc);
        float4 bv1 = *(const float4*)(Bm + (long)(k0 + br + 8) * 1152 + n0 + bc);

        __syncthreads();
        As[ar * GAST + ac + 0] = av.x;
        As[ar * GAST + ac + 1] = av.y;
        As[ar * GAST + ac + 2] = av.z;
        As[ar * GAST + ac + 3] = av.w;
        Bs[br * GBST + bc + 0] = bv0.x;
        Bs[br * GBST + bc + 1] = bv0.y;
        Bs[br * GBST + bc + 2] = bv0.z;
        Bs[br * GBST + bc + 3] = bv0.w;
        Bs[(br + 8) * GBST + bc + 0] = bv1.x;
        Bs[(br + 8) * GBST + bc + 1] = bv1.y;
        Bs[(br + 8) * GBST + bc + 2] = bv1.z;
        Bs[(br + 8) * GBST + bc + 3] = bv1.w;
        __syncthreads();

#pragma unroll
        for (int ks = 0; ks < 2; ++ks) {
            const int kk = ks * 8;
            unsigned ah[2][4], al[2][4];
#pragma unroll
            for (int mt = 0; mt < 2; ++mt) {
                const float* ap = As + (wm * 32 + mt * 16 + qr) * GAST + kk + qc;
                tf32_split(ap[0],            ah[mt][0], al[mt][0]);
                tf32_split(ap[8 * GAST],     ah[mt][1], al[mt][1]);
                tf32_split(ap[4],            ah[mt][2], al[mt][2]);
                tf32_split(ap[8 * GAST + 4], ah[mt][3], al[mt][3]);
            }
#pragma unroll
            for (int nt = 0; nt < 4; ++nt) {
                const float* bp = Bs + (kk + qc) * GBST + wn * 32 + nt * 8 + qr;
                unsigned bh0, bl0, bh1, bl1;
                tf32_split(bp[0],        bh0, bl0);
                tf32_split(bp[4 * GBST], bh1, bl1);
#pragma unroll
                for (int mt = 0; mt < 2; ++mt)
                    mma3(acc[mt][nt], ah[mt], al[mt], bh0, bh1, bl0, bl1);
            }
        }
    }

#pragma unroll
    for (int mt = 0; mt < 2; ++mt) {
        const int row = m0 + wm * 32 + mt * 16 + qr;
#pragma unroll
        for (int nt = 0; nt < 4; ++nt) {
            const int col = n0 + wn * 32 + nt * 8 + qc * 2;
            *(float2*)(C + (long)row * 1152 + col) =
                make_float2(acc[mt][nt][0], acc[mt][nt][1]);
            *(float2*)(C + (long)(row + 8) * 1152 + col) =
                make_float2(acc[mt][nt][2], acc[mt][nt][3]);
        }
    }
}

__global__ __launch_bounds__(256) void gemm_qkv_kernel(const float* __restrict__ X,
                                                       const float* __restrict__ Wq,
                                                       const float* __restrict__ Wk,
                                                       const float* __restrict__ Wv) {
    const float* B = (blockIdx.z == 0) ? Wq : (blockIdx.z == 1 ? Wk : Wv);
    float* C = (blockIdx.z == 0) ? g_q : (blockIdx.z == 1 ? g_k : g_v);
    gemm3_body(X, B, C);
}

__global__ __launch_bounds__(256) void gemm_out_kernel(const float* __restrict__ Wo,
                                                       float* __restrict__ out) {
    gemm3_body(g_ao, Wo, out);
}

// ---------------------------------------------------------------------------
// RMSNorm + 2D RoPE (unchanged from passing version)
// ---------------------------------------------------------------------------
__global__ __launch_bounds__(128) void norm_rope_kernel(const float* __restrict__ cosb,
                                                        const float* __restrict__ sinb,
                                                        const float* __restrict__ qsc,
                                                        const float* __restrict__ ksc) {
    __shared__ float bq[4][HD];
    __shared__ float bk[4][HD];

    const int w = threadIdx.x >> 5;
    const int lane = threadIdx.x & 31;
    const int pair = blockIdx.x * 4 + w;           // = n*16 + h
    const int n = pair >> 4;

    float* qp = g_q + (long)pair * HD;
    float* kp = g_k + (long)pair * HD;
    float* vp = g_v + (long)pair * HD;

    float q0 = qp[lane], q1 = qp[lane + 32], q2 = (lane < 8) ? qp[lane + 64] : 0.0f;
    float k0 = kp[lane], k1 = kp[lane + 32], k2 = (lane < 8) ? kp[lane + 64] : 0.0f;
    float v0 = vp[lane], v1 = vp[lane + 32], v2 = (lane < 8) ? vp[lane + 64] : 0.0f;

    float sq = q0 * q0 + q1 * q1 + q2 * q2;
    float sk = k0 * k0 + k1 * k1 + k2 * k2;
    float sv = v0 * v0 + v1 * v1 + v2 * v2;
#pragma unroll
    for (int o = 16; o > 0; o >>= 1) {
        sq += __shfl_xor_sync(0xffffffffu, sq, o);
        sk += __shfl_xor_sync(0xffffffffu, sk, o);
        sv += __shfl_xor_sync(0xffffffffu, sv, o);
    }
    const float iq = rsqrtf(sq * (1.0f / HD) + 1e-6f);
    const float ik = rsqrtf(sk * (1.0f / HD) + 1e-6f);
    const float iv = rsqrtf(sv * (1.0f / HD) + 1e-6f);

    vp[lane] = v0 * iv;
    vp[lane + 32] = v1 * iv;
    if (lane < 8) vp[lane + 64] = v2 * iv;

    bq[w][lane]      = q0 * iq * qsc[lane];
    bq[w][lane + 32] = q1 * iq * qsc[lane + 32];
    bk[w][lane]      = k0 * ik * ksc[lane];
    bk[w][lane + 32] = k1 * ik * ksc[lane + 32];
    if (lane < 8) {
        bq[w][lane + 64] = q2 * iq * qsc[lane + 64];
        bk[w][lane + 64] = k2 * ik * ksc[lane + 64];
    }
    __syncwarp();

    const float* cr = cosb + (long)n * HD;
    const float* sr = sinb + (long)n * HD;
#pragma unroll
    for (int e = 0; e < 3; ++e) {
        int d = lane + 32 * e;
        if (d < HD) {
            float c = cr[d], s = sr[d];
            int loc = d % 36;
            int prt = (loc < 18) ? d + 18 : d - 18;
            float sgn = (loc < 18) ? -1.0f : 1.0f;
            qp[d] = bq[w][d] * c + sgn * bq[w][prt] * s;
            kp[d] = bk[w][d] * c + sgn * bk[w][prt] * s;
        }
    }
}

// ---------------------------------------------------------------------------
// Flash attention on tensor cores (3xTF32), fp32 accuracy.
// Block: 256 thr (8 warps), BQ=64 q rows, BKV=64 kv per iter.
// S phase: warps = 4 m-groups x 2 n-groups (warp tile 16x32).
// PV phase: warps = 4 m-groups x 2 d-groups (warp tile 16x40, V padded to 80).
// Smem (dynamic, 80640 B): Q(76) K(76) V(88) P(68) + softmax stats.
// ---------------------------------------------------------------------------
#define QST 76
#define VST 88
#define PST 68
#define OQ  0
#define OK_ 4864
#define OV  9728
#define OP  15360
#define OM  19712
#define OL  19776
#define OSC 19840
#define OTM 19904
#define OTS 20032
#define ASMEM_FLOATS 20160

__global__ __launch_bounds__(256) void attn_kernel() {
    extern __shared__ float sm[];
    float* Qs   = sm + OQ;
    float* Ks   = sm + OK_;
    float* Vs   = sm + OV;
    float* Ps   = sm + OP;
    float* m_s  = sm + OM;
    float* l_s  = sm + OL;
    float* sc_s = sm + OSC;
    float* tmax = sm + OTM;   // [2][64]
    float* tsum = sm + OTS;   // [2][64]

    const int h  = blockIdx.y;
    const int q0 = blockIdx.x * 64;
    const int tid  = threadIdx.x;
    const int lane = tid & 31;
    const int wid  = tid >> 5;
    const int mg = wid >> 1;          // 0..3 (16-row group)
    const int ng = wid & 1;           // 0..1 (32-col / 40-dim group)
    const int qr = lane >> 2, qc = lane & 3;
    const int r0 = mg * 16 + qr;      // this thread's rows: r0, r0+8
    const int r1 = r0 + 8;

    // ---- Load Q tile (64 x 72) ----
    for (int idx = tid; idx < 1152; idx += 256) {     // 1152 float4
        int r = idx / 18, d4 = (idx - r * 18) * 4;
        float4 v = *(const float4*)(g_q + (long)(q0 + r) * PROJ + h * HD + d4);
        Qs[r * QST + d4 + 0] = v.x; Qs[r * QST + d4 + 1] = v.y;
        Qs[r * QST + d4 + 2] = v.z; Qs[r * QST + d4 + 3] = v.w;
    }
    // zero V pad cols 72..79 (written once; load loop never touches them)
    for (int i = tid; i < 512; i += 256)
        Vs[(i >> 3) * VST + 72 + (i & 7)] = 0.0f;
    if (tid < 64) { m_s[tid] = -1e30f; l_s[tid] = 0.0f; }

    float acc[5][4] = {};

    for (int j = 0; j < NTOK / 64; ++j) {
        const int kb = j * 64;
        __syncthreads();   // prior-iter P/V reads done; Q/stats ready (iter 0)

        // ---- Load K,V tiles (64 x 72 each) ----
        for (int idx = tid; idx < 1152; idx += 256) {
            int r = idx / 18, d4 = (idx - r * 18) * 4;
            long g = (long)(kb + r) * PROJ + h * HD + d4;
            float4 kv = *(const float4*)(g_k + g);
            float4 vv = *(const float4*)(g_v + g);
            Ks[r * QST + d4 + 0] = kv.x; Ks[r * QST + d4 + 1] = kv.y;
            Ks[r * QST + d4 + 2] = kv.z; Ks[r * QST + d4 + 3] = kv.w;
            Vs[r * VST + d4 + 0] = vv.x; Vs[r * VST + d4 + 1] = vv.y;
            Vs[r * VST + d4 + 2] = vv.z; Vs[r * VST + d4 + 3] = vv.w;
        }
        __syncthreads();

        // ---- S = Q @ K^T : warp tile rows [mg*16, +16), cols [ng*32, +32) ----
        float s[4][4] = {};
#pragma unroll
        for (int ks = 0; ks < 9; ++ks) {
            const int kk = ks * 8;
            unsigned ah[4], al[4];
            const float* ap = Qs + (long)r0 * QST + kk + qc;
            tf32_split(ap[0],           ah[0], al[0]);
            tf32_split(ap[8 * QST],     ah[1], al[1]);
            tf32_split(ap[4],           ah[2], al[2]);
            tf32_split(ap[8 * QST + 4], ah[3], al[3]);
#pragma unroll
            for (int nt = 0; nt < 4; ++nt) {
                const float* bp = Ks + (ng * 32 + nt * 8 + qr) * QST + kk + qc;
                unsigned bh0, bl0, bh1, bl1;
                tf32_split(bp[0], bh0, bl0);
                tf32_split(bp[4], bh1, bl1);
                mma3(s[nt], ah, al, bh0, bh1, bl0, bl1);
            }
        }

        // ---- online softmax: tile row-max ----
        float mx0 = -1e30f, mx1 = -1e30f;
#pragma unroll
        for (int nt = 0; nt < 4; ++nt) {
            mx0 = fmaxf(mx0, fmaxf(s[nt][0], s[nt][1]));
            mx1 = fmaxf(mx1, fmaxf(s[nt][2], s[nt][3]));
        }
        mx0 = fmaxf(mx0, __shfl_xor_sync(0xffffffffu, mx0, 1));
        mx0 = fmaxf(mx0, __shfl_xor_sync(0xffffffffu, mx0, 2));
        mx1 = fmaxf(mx1, __shfl_xor_sync(0xffffffffu, mx1, 1));
        mx1 = fmaxf(mx1, __shfl_xor_sync(0xffffffffu, mx1, 2));
        if (qc == 0) { tmax[ng * 64 + r0] = mx0; tmax[ng * 64 + r1] = mx1; }
        __syncthreads();

        if (tid < 64) {
            float mn = fmaxf(m_s[tid], fmaxf(tmax[tid], tmax[64 + tid]));
            sc_s[tid] = __expf(m_s[tid] - mn);
            m_s[tid] = mn;
        }
        __syncthreads();

        // ---- p = exp(s - m), store P, partial row sums, rescale acc ----
        {
            const float mn0 = m_s[r0], mn1 = m_s[r1];
            float sum0 = 0.0f, sum1 = 0.0f;
#pragma unroll
            for (int nt = 0; nt < 4; ++nt) {
                const int col = ng * 32 + nt * 8 + qc * 2;
                float p0 = __expf(s[nt][0] - mn0);
                float p1 = __expf(s[nt][1] - mn0);
                float p2 = __expf(s[nt][2] - mn1);
                float p3 = __expf(s[nt][3] - mn1);
                sum0 += p0 + p1;
                sum1 += p2 + p3;
                *(float2*)(Ps + r0 * PST + col) = make_float2(p0, p1);
                *(float2*)(Ps + r1 * PST + col) = make_float2(p2, p3);
            }
            sum0 += __shfl_xor_sync(0xffffffffu, sum0, 1);
            sum0 += __shfl_xor_sync(0xffffffffu, sum0, 2);
            sum1 += __shfl_xor_sync(0xffffffffu, sum1, 1);
            sum1 += __shfl_xor_sync(0xffffffffu, sum1, 2);
            if (qc == 0) { tsum[ng * 64 + r0] = sum0; tsum[ng * 64 + r1] = sum1; }

            const float sc0 = sc_s[r0], sc1 = sc_s[r1];
#pragma unroll
            for (int dt = 0; dt < 5; ++dt) {
                acc[dt][0] *= sc0; acc[dt][1] *= sc0;
                acc[dt][2] *= sc1; acc[dt][3] *= sc1;
            }
        }
        __syncthreads();

        if (tid < 64)
            l_s[tid] = l_s[tid] * sc_s[tid] + tsum[tid] + tsum[64 + tid];

        // ---- acc += P @ V : warp tile rows [mg*16,+16), dims [ng*40,+40) ----
#pragma unroll
        for (int ks = 0; ks < 8; ++ks) {
            const int kk = ks * 8;
            unsigned ah[4], al[4];
            const float* ap = Ps + (long)r0 * PST + kk + qc;
            tf32_split(ap[0],           ah[0], al[0]);
            tf32_split(ap[8 * PST],     ah[1], al[1]);
            tf32_split(ap[4],           ah[2], al[2]);
            tf32_split(ap[8 * PST + 4], ah[3], al[3]);
#pragma unroll
            for (int dt = 0; dt < 5; ++dt) {
                const float* bp = Vs + (kk + qc) * VST + ng * 40 + dt * 8 + qr;
                unsigned bh0, bl0, bh1, bl1;
                tf32_split(bp[0],       bh0, bl0);
                tf32_split(bp[4 * VST], bh1, bl1);
                mma3(acc[dt], ah, al, bh0, bh1, bl0, bl1);
            }
        }
    }

    __syncthreads();   // final l_s writes visible
    const float il0 = 1.0f / l_s[r0];
    const float il1 = 1.0f / l_s[r1];
#pragma unroll
    for (int dt = 0; dt < 5; ++dt) {
        const int d = ng * 40 + dt * 8 + qc * 2;
        if (d < HD) {
            *(float2*)(g_ao + (long)(q0 + r0) * PROJ + h * HD + d) =
                make_float2(acc[dt][0] * il0, acc[dt][1] * il0);
            *(float2*)(g_ao + (long)(q0 + r1) * PROJ + h * HD + d) =
                make_float2(acc[dt][2] * il1, acc[dt][3] * il1);
        }
    }
}

// ---------------------------------------------------------------------------
extern "C" void kernel_launch(void* const* d_in, const int* in_sizes, int n_in,
                              void* d_out, int out_size) {
    const float* X    = (const float*)d_in[0];
    const float* cosb = (const float*)d_in[1];
    const float* sinb = (const float*)d_in[2];
    const float* Wq   = (const float*)d_in[3];
    const float* Wk   = (const float*)d_in[4];
    const float* Wv   = (const float*)d_in[5];
    const float* Wo   = (const float*)d_in[6];
    const float* qsc  = (const float*)d_in[7];
    const float* ksc  = (const float*)d_in[8];
    float* out = (float*)d_out;

    const int asmem = ASMEM_FLOATS * (int)sizeof(float);   // 80640 B
    cudaFuncSetAttribute(attn_kernel, cudaFuncAttributeMaxDynamicSharedMemorySize, asmem);

    gemm_qkv_kernel<<<dim3(PROJ / 128, NTOK / 64, 3), 256>>>(X, Wq, Wk, Wv);
    norm_rope_kernel<<<(NTOK * NH) / 4, 128>>>(cosb, sinb, qsc, ksc);
    attn_kernel<<<dim3(NTOK / 64, NH), 256, asmem>>>();
    gemm_out_kernel<<<dim3(HID / 128, NTOK / 64), 256>>>(Wo, out);
}

// round 4
// speedup vs baseline: 2.1863x; 1.3901x over previous
#include <cuda_runtime.h>
#include <cuda_bf16.h>
#include <math.h>

#define NTOK 4096
#define NH   16
#define HD   72
#define HID  1152
#define PROJ 1152

// Scratch (allowed: __device__ globals, no runtime allocation)
__device__ float    g_q [NTOK * PROJ];   // raw QKV gemm outputs (pre-norm)
__device__ float    g_k [NTOK * PROJ];
__device__ float    g_v [NTOK * PROJ];
__device__ unsigned g_qp[NTOK * PROJ];   // packed (bf16 hi, bf16 lo) post norm/rope
__device__ unsigned g_kp[NTOK * PROJ];
__device__ unsigned g_vp[NTOK * PROJ];
__device__ unsigned g_aop[NTOK * PROJ];  // packed attention output
__device__ unsigned g_xp[NTOK * HID];    // packed hidden_states
__device__ unsigned g_wq[HID * PROJ];    // packed weights
__device__ unsigned g_wk[HID * PROJ];
__device__ unsigned g_wv[HID * PROJ];
__device__ unsigned g_wo[PROJ * HID];

// ---------------------------------------------------------------------------
// pack: fp32 -> u32 holding (lo16 half = bf16 hi part, hi16 half = bf16 residual)
// Interleaved along k, mma.m16n8k16 over the pair-slots computes ah*bh + al*bl;
// a second mma with A's halves swapped adds al*bh + ah*bl -> full 4-term product.
// ---------------------------------------------------------------------------
__device__ __forceinline__ unsigned pack2(float x) {
    unsigned short hb = __bfloat16_as_ushort(__float2bfloat16_rn(x));
    float hf = __uint_as_float(((unsigned)hb) << 16);
    unsigned short lb = __bfloat16_as_ushort(__float2bfloat16_rn(x - hf));
    return (((unsigned)lb) << 16) | (unsigned)hb;
}

__device__ __forceinline__ void mma_bf16(float d[4], const unsigned a[4],
                                         unsigned b0, unsigned b1) {
    asm volatile(
        "mma.sync.aligned.m16n8k16.row.col.f32.bf16.bf16.f32 "
        "{%0,%1,%2,%3}, {%4,%5,%6,%7}, {%8,%9}, {%0,%1,%2,%3};\n"
        : "+f"(d[0]), "+f"(d[1]), "+f"(d[2]), "+f"(d[3])
        : "r"(a[0]), "r"(a[1]), "r"(a[2]), "r"(a[3]), "r"(b0), "r"(b1));
}

__device__ __forceinline__ void swap_frag(unsigned s[4], const unsigned a[4]) {
#pragma unroll
    for (int i = 0; i < 4; ++i) s[i] = __byte_perm(a[i], a[i], 0x1032);
}

__global__ __launch_bounds__(256) void pack_kernel(const float* __restrict__ src,
                                                   unsigned* __restrict__ dst, int n4) {
    int i = blockIdx.x * 256 + threadIdx.x;
    if (i < n4) {
        float4 v = ((const float4*)src)[i];
        uint4 o;
        o.x = pack2(v.x); o.y = pack2(v.y); o.z = pack2(v.z); o.w = pack2(v.w);
        ((uint4*)dst)[i] = o;
    }
}

// ---------------------------------------------------------------------------
// Packed bf16 dual-mma GEMM: C[4096,1152] = A @ B (both pre-packed).
// Block 256 thr (8 warps 2x4), tile 64x128, BK=16 real k. Warp tile 32x32.
// ---------------------------------------------------------------------------
#define GAST 20
#define GBST 136

__device__ __forceinline__ void gemm4_body(const unsigned* __restrict__ A,
                                           const unsigned* __restrict__ Bm,
                                           float* __restrict__ C) {
    __shared__ unsigned As[64 * GAST];
    __shared__ unsigned Bs[16 * GBST];

    const int tid  = threadIdx.x;
    const int lane = tid & 31;
    const int wid  = tid >> 5;
    const int wm = wid >> 2, wn = wid & 3;
    const int qr = lane >> 2, qc = lane & 3;

    const int m0 = blockIdx.y * 64;
    const int n0 = blockIdx.x * 128;

    const int ar = tid >> 2;
    const int ac = (tid & 3) * 4;
    const int br = tid >> 5;
    const int bc = (tid & 31) * 4;

    float acc[2][4][4] = {};

    for (int k0 = 0; k0 < 1152; k0 += 16) {
        uint4 av  = *(const uint4*)(A  + (long)(m0 + ar) * 1152 + k0 + ac);
        uint4 bv0 = *(const uint4*)(Bm + (long)(k0 + br) * 1152 + n0 + bc);
        uint4 bv1 = *(const uint4*)(Bm + (long)(k0 + br + 8) * 1152 + n0 + bc);

        __syncthreads();
        As[ar * GAST + ac + 0] = av.x;
        As[ar * GAST + ac + 1] = av.y;
        As[ar * GAST + ac + 2] = av.z;
        As[ar * GAST + ac + 3] = av.w;
        Bs[br * GBST + bc + 0] = bv0.x;
        Bs[br * GBST + bc + 1] = bv0.y;
        Bs[br * GBST + bc + 2] = bv0.z;
        Bs[br * GBST + bc + 3] = bv0.w;
        Bs[(br + 8) * GBST + bc + 0] = bv1.x;
        Bs[(br + 8) * GBST + bc + 1] = bv1.y;
        Bs[(br + 8) * GBST + bc + 2] = bv1.z;
        Bs[(br + 8) * GBST + bc + 3] = bv1.w;
        __syncthreads();

#pragma unroll
        for (int ks = 0; ks < 2; ++ks) {
            const int kk = ks * 8;
            unsigned ai[2][4], asw[2][4];
#pragma unroll
            for (int mt = 0; mt < 2; ++mt) {
                const unsigned* ap = As + (wm * 32 + mt * 16 + qr) * GAST + kk + qc;
                ai[mt][0] = ap[0];
                ai[mt][1] = ap[8 * GAST];
                ai[mt][2] = ap[4];
                ai[mt][3] = ap[8 * GAST + 4];
                swap_frag(asw[mt], ai[mt]);
            }
#pragma unroll
            for (int nt = 0; nt < 4; ++nt) {
                const unsigned* bp = Bs + (kk + qc) * GBST + wn * 32 + nt * 8 + qr;
                unsigned b0 = bp[0];
                unsigned b1 = bp[4 * GBST];
#pragma unroll
                for (int mt = 0; mt < 2; ++mt) {
                    mma_bf16(acc[mt][nt], ai[mt],  b0, b1);
                    mma_bf16(acc[mt][nt], asw[mt], b0, b1);
                }
            }
        }
    }

#pragma unroll
    for (int mt = 0; mt < 2; ++mt) {
        const int row = m0 + wm * 32 + mt * 16 + qr;
#pragma unroll
        for (int nt = 0; nt < 4; ++nt) {
            const int col = n0 + wn * 32 + nt * 8 + qc * 2;
            *(float2*)(C + (long)row * 1152 + col) =
                make_float2(acc[mt][nt][0], acc[mt][nt][1]);
            *(float2*)(C + (long)(row + 8) * 1152 + col) =
                make_float2(acc[mt][nt][2], acc[mt][nt][3]);
        }
    }
}

__global__ __launch_bounds__(256) void gemm_qkv_kernel() {
    const unsigned* B = (blockIdx.z == 0) ? g_wq : (blockIdx.z == 1 ? g_wk : g_wv);
    float* C = (blockIdx.z == 0) ? g_q : (blockIdx.z == 1 ? g_k : g_v);
    gemm4_body(g_xp, B, C);
}

__global__ __launch_bounds__(256) void gemm_out_kernel(float* __restrict__ out) {
    gemm4_body(g_aop, g_wo, out);
}

// ---------------------------------------------------------------------------
// RMSNorm + 2D RoPE; writes PACKED q/k/v.
// ---------------------------------------------------------------------------
__global__ __launch_bounds__(128) void norm_rope_kernel(const float* __restrict__ cosb,
                                                        const float* __restrict__ sinb,
                                                        const float* __restrict__ qsc,
                                                        const float* __restrict__ ksc) {
    __shared__ float bq[4][HD];
    __shared__ float bk[4][HD];

    const int w = threadIdx.x >> 5;
    const int lane = threadIdx.x & 31;
    const int pair = blockIdx.x * 4 + w;           // = n*16 + h
    const int n = pair >> 4;

    const float* qp = g_q + (long)pair * HD;
    const float* kp = g_k + (long)pair * HD;
    const float* vp = g_v + (long)pair * HD;

    float q0 = qp[lane], q1 = qp[lane + 32], q2 = (lane < 8) ? qp[lane + 64] : 0.0f;
    float k0 = kp[lane], k1 = kp[lane + 32], k2 = (lane < 8) ? kp[lane + 64] : 0.0f;
    float v0 = vp[lane], v1 = vp[lane + 32], v2 = (lane < 8) ? vp[lane + 64] : 0.0f;

    float sq = q0 * q0 + q1 * q1 + q2 * q2;
    float sk = k0 * k0 + k1 * k1 + k2 * k2;
    float sv = v0 * v0 + v1 * v1 + v2 * v2;
#pragma unroll
    for (int o = 16; o > 0; o >>= 1) {
        sq += __shfl_xor_sync(0xffffffffu, sq, o);
        sk += __shfl_xor_sync(0xffffffffu, sk, o);
        sv += __shfl_xor_sync(0xffffffffu, sv, o);
    }
    const float iq = rsqrtf(sq * (1.0f / HD) + 1e-6f);
    const float ik = rsqrtf(sk * (1.0f / HD) + 1e-6f);
    const float iv = rsqrtf(sv * (1.0f / HD) + 1e-6f);

    unsigned* vd = g_vp + (long)pair * HD;
    vd[lane]      = pack2(v0 * iv);
    vd[lane + 32] = pack2(v1 * iv);
    if (lane < 8) vd[lane + 64] = pack2(v2 * iv);

    bq[w][lane]      = q0 * iq * qsc[lane];
    bq[w][lane + 32] = q1 * iq * qsc[lane + 32];
    bk[w][lane]      = k0 * ik * ksc[lane];
    bk[w][lane + 32] = k1 * ik * ksc[lane + 32];
    if (lane < 8) {
        bq[w][lane + 64] = q2 * iq * qsc[lane + 64];
        bk[w][lane + 64] = k2 * ik * ksc[lane + 64];
    }
    __syncwarp();

    unsigned* qd = g_qp + (long)pair * HD;
    unsigned* kd = g_kp + (long)pair * HD;
    const float* cr = cosb + (long)n * HD;
    const float* sr = sinb + (long)n * HD;
#pragma unroll
    for (int e = 0; e < 3; ++e) {
        int d = lane + 32 * e;
        if (d < HD) {
            float c = cr[d], s = sr[d];
            int loc = d % 36;
            int prt = (loc < 18) ? d + 18 : d - 18;
            float sgn = (loc < 18) ? -1.0f : 1.0f;
            qd[d] = pack2(bq[w][d] * c + sgn * bq[w][prt] * s);
            kd[d] = pack2(bk[w][d] * c + sgn * bk[w][prt] * s);
        }
    }
}

// ---------------------------------------------------------------------------
// Flash attention on packed bf16 dual-mma, fp32-class accuracy.
// Block: 256 thr (8 warps), BQ=64, BKV=64.
// ---------------------------------------------------------------------------
#define QST 76
#define VST 88
#define PST 68
#define OQ  0
#define OK_ 4864
#define OV  9728
#define OP  15360
#define OM  19712
#define OL  19776
#define OSC 19840
#define OTM 19904
#define OTS 20032
#define ASMEM_WORDS 20160

__global__ __launch_bounds__(256) void attn_kernel() {
    extern __shared__ unsigned smu[];
    unsigned* Qs = smu + OQ;
    unsigned* Ks = smu + OK_;
    unsigned* Vs = smu + OV;
    unsigned* Ps = smu + OP;
    float* m_s  = (float*)(smu + OM);
    float* l_s  = (float*)(smu + OL);
    float* sc_s = (float*)(smu + OSC);
    float* tmax = (float*)(smu + OTM);   // [2][64]
    float* tsum = (float*)(smu + OTS);   // [2][64]

    const int h  = blockIdx.y;
    const int q0 = blockIdx.x * 64;
    const int tid  = threadIdx.x;
    const int lane = tid & 31;
    const int wid  = tid >> 5;
    const int mg = wid >> 1;
    const int ng = wid & 1;
    const int qr = lane >> 2, qc = lane & 3;
    const int r0 = mg * 16 + qr;
    const int r1 = r0 + 8;

    // ---- Load Q tile (64 x 72 packed) ----
    for (int idx = tid; idx < 1152; idx += 256) {
        int r = idx / 18, d4 = (idx - r * 18) * 4;
        uint4 v = *(const uint4*)(g_qp + (long)(q0 + r) * PROJ + h * HD + d4);
        Qs[r * QST + d4 + 0] = v.x; Qs[r * QST + d4 + 1] = v.y;
        Qs[r * QST + d4 + 2] = v.z; Qs[r * QST + d4 + 3] = v.w;
    }
    // zero V pad cols 72..79
    for (int i = tid; i < 512; i += 256)
        Vs[(i >> 3) * VST + 72 + (i & 7)] = 0u;
    if (tid < 64) { m_s[tid] = -1e30f; l_s[tid] = 0.0f; }

    float acc[5][4] = {};

    for (int j = 0; j < NTOK / 64; ++j) {
        const int kb = j * 64;
        __syncthreads();

        for (int idx = tid; idx < 1152; idx += 256) {
            int r = idx / 18, d4 = (idx - r * 18) * 4;
            long g = (long)(kb + r) * PROJ + h * HD + d4;
            uint4 kv = *(const uint4*)(g_kp + g);
            uint4 vv = *(const uint4*)(g_vp + g);
            Ks[r * QST + d4 + 0] = kv.x; Ks[r * QST + d4 + 1] = kv.y;
            Ks[r * QST + d4 + 2] = kv.z; Ks[r * QST + d4 + 3] = kv.w;
            Vs[r * VST + d4 + 0] = vv.x; Vs[r * VST + d4 + 1] = vv.y;
            Vs[r * VST + d4 + 2] = vv.z; Vs[r * VST + d4 + 3] = vv.w;
        }
        __syncthreads();

        // ---- S = Q @ K^T ----
        float s[4][4] = {};
#pragma unroll
        for (int ks = 0; ks < 9; ++ks) {
            const int kk = ks * 8;
            unsigned ai[4], asw[4];
            const unsigned* ap = Qs + (long)r0 * QST + kk + qc;
            ai[0] = ap[0];
            ai[1] = ap[8 * QST];
            ai[2] = ap[4];
            ai[3] = ap[8 * QST + 4];
            swap_frag(asw, ai);
#pragma unroll
            for (int nt = 0; nt < 4; ++nt) {
                const unsigned* bp = Ks + (ng * 32 + nt * 8 + qr) * QST + kk + qc;
                unsigned b0 = bp[0];
                unsigned b1 = bp[4];
                mma_bf16(s[nt], ai,  b0, b1);
                mma_bf16(s[nt], asw, b0, b1);
            }
        }

        // ---- online softmax: tile row-max ----
        float mx0 = -1e30f, mx1 = -1e30f;
#pragma unroll
        for (int nt = 0; nt < 4; ++nt) {
            mx0 = fmaxf(mx0, fmaxf(s[nt][0], s[nt][1]));
            mx1 = fmaxf(mx1, fmaxf(s[nt][2], s[nt][3]));
        }
        mx0 = fmaxf(mx0, __shfl_xor_sync(0xffffffffu, mx0, 1));
        mx0 = fmaxf(mx0, __shfl_xor_sync(0xffffffffu, mx0, 2));
        mx1 = fmaxf(mx1, __shfl_xor_sync(0xffffffffu, mx1, 1));
        mx1 = fmaxf(mx1, __shfl_xor_sync(0xffffffffu, mx1, 2));
        if (qc == 0) { tmax[ng * 64 + r0] = mx0; tmax[ng * 64 + r1] = mx1; }
        __syncthreads();

        if (tid < 64) {
            float mn = fmaxf(m_s[tid], fmaxf(tmax[tid], tmax[64 + tid]));
            sc_s[tid] = __expf(m_s[tid] - mn);
            m_s[tid] = mn;
        }
        __syncthreads();

        // ---- p = exp(s - m), store packed P, partial row sums, rescale acc ----
        {
            const float mn0 = m_s[r0], mn1 = m_s[r1];
            float sum0 = 0.0f, sum1 = 0.0f;
#pragma unroll
            for (int nt = 0; nt < 4; ++nt) {
                const int col = ng * 32 + nt * 8 + qc * 2;
                float p0 = __expf(s[nt][0] - mn0);
                float p1 = __expf(s[nt][1] - mn0);
                float p2 = __expf(s[nt][2] - mn1);
                float p3 = __expf(s[nt][3] - mn1);
                sum0 += p0 + p1;
                sum1 += p2 + p3;
                uint2 w0; w0.x = pack2(p0); w0.y = pack2(p1);
                uint2 w1; w1.x = pack2(p2); w1.y = pack2(p3);
                *(uint2*)(Ps + r0 * PST + col) = w0;
                *(uint2*)(Ps + r1 * PST + col) = w1;
            }
            sum0 += __shfl_xor_sync(0xffffffffu, sum0, 1);
            sum0 += __shfl_xor_sync(0xffffffffu, sum0, 2);
            sum1 += __shfl_xor_sync(0xffffffffu, sum1, 1);
            sum1 += __shfl_xor_sync(0xffffffffu, sum1, 2);
            if (qc == 0) { tsum[ng * 64 + r0] = sum0; tsum[ng * 64 + r1] = sum1; }

            const float sc0 = sc_s[r0], sc1 = sc_s[r1];
#pragma unroll
            for (int dt = 0; dt < 5; ++dt) {
                acc[dt][0] *= sc0; acc[dt][1] *= sc0;
                acc[dt][2] *= sc1; acc[dt][3] *= sc1;
            }
        }
        __syncthreads();

        if (tid < 64)
            l_s[tid] = l_s[tid] * sc_s[tid] + tsum[tid] + tsum[64 + tid];

        // ---- acc += P @ V ----
#pragma unroll
        for (int ks = 0; ks < 8; ++ks) {
            const int kk = ks * 8;
            unsigned ai[4], asw[4];
            const unsigned* ap = Ps + (long)r0 * PST + kk + qc;
            ai[0] = ap[0];
            ai[1] = ap[8 * PST];
            ai[2] = ap[4];
            ai[3] = ap[8 * PST + 4];
            swap_frag(asw, ai);
#pragma unroll
            for (int dt = 0; dt < 5; ++dt) {
                const unsigned* bp = Vs + (kk + qc) * VST + ng * 40 + dt * 8 + qr;
                unsigned b0 = bp[0];
                unsigned b1 = bp[4 * VST];
                mma_bf16(acc[dt], ai,  b0, b1);
                mma_bf16(acc[dt], asw, b0, b1);
            }
        }
    }

    __syncthreads();
    const float il0 = 1.0f / l_s[r0];
    const float il1 = 1.0f / l_s[r1];
#pragma unroll
    for (int dt = 0; dt < 5; ++dt) {
        const int d = ng * 40 + dt * 8 + qc * 2;
        if (d < HD) {
            uint2 w0; w0.x = pack2(acc[dt][0] * il0); w0.y = pack2(acc[dt][1] * il0);
            uint2 w1; w1.x = pack2(acc[dt][2] * il1); w1.y = pack2(acc[dt][3] * il1);
            *(uint2*)(g_aop + (long)(q0 + r0) * PROJ + h * HD + d) = w0;
            *(uint2*)(g_aop + (long)(q0 + r1) * PROJ + h * HD + d) = w1;
        }
    }
}

// ---------------------------------------------------------------------------
extern "C" void kernel_launch(void* const* d_in, const int* in_sizes, int n_in,
                              void* d_out, int out_size) {
    const float* X    = (const float*)d_in[0];
    const float* cosb = (const float*)d_in[1];
    const float* sinb = (const float*)d_in[2];
    const float* Wq   = (const float*)d_in[3];
    const float* Wk   = (const float*)d_in[4];
    const float* Wv   = (const float*)d_in[5];
    const float* Wo   = (const float*)d_in[6];
    const float* qsc  = (const float*)d_in[7];
    const float* ksc  = (const float*)d_in[8];
    float* out = (float*)d_out;

    const int asmem = ASMEM_WORDS * (int)sizeof(unsigned);   // 80640 B
    cudaFuncSetAttribute(attn_kernel, cudaFuncAttributeMaxDynamicSharedMemorySize, asmem);

    unsigned* xp; cudaGetSymbolAddress((void**)&xp, g_xp);
    unsigned* wq; cudaGetSymbolAddress((void**)&wq, g_wq);
    unsigned* wk; cudaGetSymbolAddress((void**)&wk, g_wk);
    unsigned* wv; cudaGetSymbolAddress((void**)&wv, g_wv);
    unsigned* wo; cudaGetSymbolAddress((void**)&wo, g_wo);

    const int nx4 = NTOK * HID / 4;
    const int nw4 = HID * PROJ / 4;
    pack_kernel<<<(nx4 + 255) / 256, 256>>>(X,  xp, nx4);
    pack_kernel<<<(nw4 + 255) / 256, 256>>>(Wq, wq, nw4);
    pack_kernel<<<(nw4 + 255) / 256, 256>>>(Wk, wk, nw4);
    pack_kernel<<<(nw4 + 255) / 256, 256>>>(Wv, wv, nw4);
    pack_kernel<<<(nw4 + 255) / 256, 256>>>(Wo, wo, nw4);

    gemm_qkv_kernel<<<dim3(PROJ / 128, NTOK / 64, 3), 256>>>();
    norm_rope_kernel<<<(NTOK * NH) / 4, 128>>>(cosb, sinb, qsc, ksc);
    attn_kernel<<<dim3(NTOK / 64, NH), 256, asmem>>>();
    gemm_out_kernel<<<dim3(HID / 128, NTOK / 64), 256>>>(out);
}